// round 4
// baseline (speedup 1.0000x reference)
#include <cuda_runtime.h>
#include <cstdint>

#define HH 512
#define WW 512
#define MAXB 16
#define MAXBN 512          // max B*N slabs
#define NCH 4              // H-chunks per slab
#define CHROWS (HH / NCH)  // 128 rows per chunk

// Scratch (device globals — zero-initialized at module load; no allocation).
__device__ int   g_xmin [MAXB * HH];
__device__ int   g_xmax [MAXB * HH];
__device__ float g_unit [MAXB * HH];
__device__ float g_unit2[MAXB * HH];
__device__ int   g_count[MAXB];                 // minmax->fit election
__device__ float g_colp [MAXBN][NCH][WW];       // per-chunk column sums
__device__ float g_part [MAXBN][NCH][2];        // per-chunk {inst, vert}
__device__ int   g_cnt  [MAXBN];                // size-chunk election

// ---------------------------------------------------------------------------
// Kernel A: per-row min/max positive column of seg channel 1, fused with the
// trimmed weighted-LS fit (done by the last block to finish per image).
// Grid = B*32 blocks; block = 512 thr = 16 warps; warp owns one row (float4).
// ---------------------------------------------------------------------------
__global__ void __launch_bounds__(512) minmax_fit_kernel(const float* __restrict__ seg)
{
    const int b    = blockIdx.x >> 5;
    const int blk  = blockIdx.x & 31;
    const int tid  = threadIdx.x;
    const int lane = tid & 31;
    const int warp = tid >> 5;

    const int h = blk * 16 + warp;
    const float4* row = (const float4*)(seg + (size_t)b * HH * WW * 2
                                            + (size_t)h * WW * 2);
    int mn = WW, mx = -1;
    #pragma unroll
    for (int i = 0; i < 8; i++) {
        const int j = lane + i * 32;        // float4 index 0..255
        const float4 v = row[j];            // pixels 2j (x=ch0,y=ch1), 2j+1 (z,w)
        if (v.y > 0.0f) { mn = min(mn, 2 * j);     mx = max(mx, 2 * j); }
        if (v.w > 0.0f) { mn = min(mn, 2 * j + 1); mx = max(mx, 2 * j + 1); }
    }
    #pragma unroll
    for (int o = 16; o; o >>= 1) {
        mn = min(mn, __shfl_down_sync(0xffffffffu, mn, o));
        mx = max(mx, __shfl_down_sync(0xffffffffu, mx, o));
    }
    if (lane == 0) {
        g_xmin[b * HH + h] = mn;
        g_xmax[b * HH + h] = mx;
    }

    // ---- elect the last block of this image to run the fit ----
    __shared__ int isLast;
    __syncthreads();
    if (tid == 0) {
        __threadfence();
        isLast = (atomicAdd(&g_count[b], 1) == 31);
    }
    __syncthreads();
    if (!isLast) return;
    __threadfence();

    const int xmin_i = __ldcg(&g_xmin[b * HH + tid]);
    const int xmax_i = __ldcg(&g_xmax[b * HH + tid]);
    const int valid  = (xmax_i >= 0 && xmin_i != xmax_i) ? 1 : 0;

    __shared__ int wtot[16];
    unsigned bal = __ballot_sync(0xffffffffu, valid);
    int pre = __popc(bal & ((1u << lane) - 1u));
    if (lane == 0) wtot[warp] = __popc(bal);
    __syncthreads();

    int off = 0, nvalid = 0;
    #pragma unroll
    for (int i = 0; i < 16; i++) {
        int t = wtot[i];
        nvalid += t;
        if (i < warp) off += t;
    }
    const int rank = off + pre;

    int drop = (int)((float)nvalid * 0.15f);   // trunc, matches astype(int32)
    if (drop < 1) drop = 1;
    const int keep = valid && (rank >= drop) && (rank < nvalid - drop);

    const float w  = keep ? 1.0f : 0.0f;
    const float y  = (float)tid;
    const float xl = (float)xmin_i;
    const float xr = (float)xmax_i;

    float v0 = w;
    float v1 = w * y;
    float v2 = w * y * y;
    float v3 = w * xl;
    float v4 = w * y * xl;
    float v5 = w * xr;
    float v6 = w * y * xr;

    __shared__ float acc[7];
    if (tid < 7) acc[tid] = 0.0f;
    __syncthreads();

    #pragma unroll
    for (int o = 16; o; o >>= 1) {
        v0 += __shfl_down_sync(0xffffffffu, v0, o);
        v1 += __shfl_down_sync(0xffffffffu, v1, o);
        v2 += __shfl_down_sync(0xffffffffu, v2, o);
        v3 += __shfl_down_sync(0xffffffffu, v3, o);
        v4 += __shfl_down_sync(0xffffffffu, v4, o);
        v5 += __shfl_down_sync(0xffffffffu, v5, o);
        v6 += __shfl_down_sync(0xffffffffu, v6, o);
    }
    if (lane == 0) {
        atomicAdd(&acc[0], v0);
        atomicAdd(&acc[1], v1);
        atomicAdd(&acc[2], v2);
        atomicAdd(&acc[3], v3);
        atomicAdd(&acc[4], v4);
        atomicAdd(&acc[5], v5);
        atomicAdd(&acc[6], v6);
    }
    __syncthreads();

    const float Sw  = acc[0], Sy  = acc[1], Syy = acc[2];
    const float Sxl = acc[3], Sxyl = acc[4];
    const float Sxr = acc[5], Sxyr = acc[6];

    const float det  = Syy * Sw - Sy * Sy;
    const float safe = (det > 0.0f) ? det : 1.0f;

    float sl_l = (Sw * Sxyl - Sy * Sxl) / safe;
    float ic_l = (-Sy * Sxyl + Syy * Sxl) / safe;
    float sl_r = (Sw * Sxyr - Sy * Sxr) / safe;
    float ic_r = (-Sy * Sxyr + Syy * Sxr) / safe;
    if (!(det > 0.0f)) { sl_l = ic_l = sl_r = ic_r = 0.0f; }

    float width = (y * sl_r + ic_r) - (y * sl_l + ic_l);
    width = fmaxf(width, 1.0f);
    const float u = 3.25f / width;

    g_unit [b * HH + tid] = u;
    g_unit2[b * HH + tid] = u * u;

    if (tid == 0) g_count[b] = 0;    // reset for the next graph replay
}

// ---------------------------------------------------------------------------
// Kernel C: one block per (bn, chunk); chunk = 128 consecutive rows of the
// [H, W] slab. 512 threads = 4 row-groups x 128 col-threads; thread (g, c)
// owns columns 4c..4c+3, local rows g, g+4, ..., g+124 (32 iterations).
// Partials go to dedicated scratch slots (deterministic combine); the last
// block per slab combines all 4 chunks and writes out[bn].
// ---------------------------------------------------------------------------
__global__ void __launch_bounds__(512) size_kernel(const float* __restrict__ pad,
                                                   float* __restrict__ out,
                                                   int N)
{
    const int bn   = blockIdx.x >> 2;
    const int ch   = blockIdx.x & 3;
    const int b    = bn / N;
    const int tid  = threadIdx.x;
    const int lane = tid & 31;
    const int warp = tid >> 5;
    const int g    = tid >> 7;        // row group 0..3
    const int c    = tid & 127;       // column group: columns 4c..4c+3

    const int h0 = ch * CHROWS;       // first global row of this chunk

    __shared__ float    su [CHROWS];
    __shared__ float    su2[CHROWS];
    __shared__ float    scol[WW];
    __shared__ unsigned grpmask[4];   // 32-bit per row-group occupied mask
    __shared__ float    sred[16];

    if (tid < CHROWS) {
        su [tid] = g_unit [b * HH + h0 + tid];
        su2[tid] = g_unit2[b * HH + h0 + tid];
    }
    scol[tid] = 0.0f;
    if (tid < 4) grpmask[tid] = 0u;
    __syncthreads();

    const float4* p = (const float4*)(pad + (size_t)bn * HH * WW
                                          + (size_t)h0 * WW) + c;

    float4 colacc = make_float4(0.f, 0.f, 0.f, 0.f);
    float  inst   = 0.0f;
    unsigned lm   = 0u;

    #pragma unroll 8
    for (int k = 0; k < 32; k++) {
        const int h = g + 4 * k;      // local row
        const float4 v = p[(size_t)h * (WW / 4)];
        const float u1 = su[h], u2 = su2[h];
        colacc.x = fmaf(u1, v.x, colacc.x);
        colacc.y = fmaf(u1, v.y, colacc.y);
        colacc.z = fmaf(u1, v.z, colacc.z);
        colacc.w = fmaf(u1, v.w, colacc.w);
        inst = fmaf(u2, (v.x + v.y) + (v.z + v.w), inst);
        if (v.x > 0.5f || v.y > 0.5f || v.z > 0.5f || v.w > 0.5f)
            lm |= (1u << k);
    }

    // row-occupied bits: OR across the 4 warps of each group
    {
        unsigned m = __reduce_or_sync(0xffffffffu, lm);
        if (lane == 0 && m) atomicOr(&grpmask[g], m);
    }

    // per-column sums: combine 4 groups via shared atomics
    atomicAdd(&scol[4 * c + 0], colacc.x);
    atomicAdd(&scol[4 * c + 1], colacc.y);
    atomicAdd(&scol[4 * c + 2], colacc.z);
    atomicAdd(&scol[4 * c + 3], colacc.w);

    // instance partial (block sum)
    float s = inst;
    #pragma unroll
    for (int o = 16; o; o >>= 1) s += __shfl_down_sync(0xffffffffu, s, o);
    if (lane == 0) sred[warp] = s;
    __syncthreads();

    // vertical partial: local row r handled by group r&3, iteration r>>2
    float vv = 0.0f;
    if (tid < CHROWS) {
        const unsigned bit = (grpmask[tid & 3] >> (tid >> 2)) & 1u;
        vv = bit ? su[tid] : 0.0f;
    }
    #pragma unroll
    for (int o = 16; o; o >>= 1) vv += __shfl_down_sync(0xffffffffu, vv, o);

    __shared__ float svert[4];
    if (lane == 0 && warp < 4) svert[warp] = vv;
    __syncthreads();

    if (tid == 0) {
        float ti = 0.0f;
        #pragma unroll
        for (int i = 0; i < 16; i++) ti += sred[i];
        float tv = (svert[0] + svert[1]) + (svert[2] + svert[3]);
        g_part[bn][ch][0] = ti;
        g_part[bn][ch][1] = tv;
    }

    // column partials to scratch (coalesced, 1 per thread)
    g_colp[bn][ch][tid] = scol[tid];

    // ---- elect last chunk-block of this slab to combine ----
    __shared__ int isLast;
    __syncthreads();
    if (tid == 0) {
        __threadfence();
        isLast = (atomicAdd(&g_cnt[bn], 1) == NCH - 1);
    }
    __syncthreads();
    if (!isLast) return;
    __threadfence();

    // horizontal: per-column sum over chunks (fixed order), then block max
    float colsum = __ldcg(&g_colp[bn][0][tid]);
    colsum += __ldcg(&g_colp[bn][1][tid]);
    colsum += __ldcg(&g_colp[bn][2][tid]);
    colsum += __ldcg(&g_colp[bn][3][tid]);

    float m = colsum;
    #pragma unroll
    for (int o = 16; o; o >>= 1) m = fmaxf(m, __shfl_down_sync(0xffffffffu, m, o));
    if (lane == 0) sred[warp] = m;
    __syncthreads();

    if (tid == 0) {
        float hmax = sred[0];
        #pragma unroll
        for (int i = 1; i < 16; i++) hmax = fmaxf(hmax, sred[i]);

        float ti = 0.0f, tv = 0.0f;
        #pragma unroll
        for (int i = 0; i < NCH; i++) {
            ti += __ldcg(&g_part[bn][i][0]);
            tv += __ldcg(&g_part[bn][i][1]);
        }
        out[bn * 3 + 0] = ti;
        out[bn * 3 + 1] = hmax;
        out[bn * 3 + 2] = tv;

        g_cnt[bn] = 0;               // reset for the next graph replay
    }
}

// ---------------------------------------------------------------------------
extern "C" void kernel_launch(void* const* d_in, const int* in_sizes, int n_in,
                              void* d_out, int out_size)
{
    const float* seg = (const float*)d_in[0];   // [B, H, W, 2]
    const float* pad = (const float*)d_in[1];   // [B, N, H, W]
    float* out = (float*)d_out;                 // [B, N, 3]

    const int B = in_sizes[0] / (HH * WW * 2);
    const int N = in_sizes[1] / (B * HH * WW);

    minmax_fit_kernel<<<B * 32, 512>>>(seg);
    size_kernel<<<B * N * NCH, 512>>>(pad, out, N);
}